// round 11
// baseline (speedup 1.0000x reference)
#include <cuda_runtime.h>
#include <cstdint>

typedef unsigned long long ull;
typedef unsigned int uint;

#define D_IN   4096
#define R_RANK 16
#define O_OUT  4096
#define M_TOT  8192
#define SCALE  2.0f          // alpha/rank = 32/16
#define KC     64            // K floats per pipeline chunk
#define NITER  (D_IN / KC)   // 64
#define MT     64            // tokens per CTA (p1)
#define TOK2   64            // tokens per CTA (p2)

// ---- device scratch ----
__device__ __align__(16) ull g_h[M_TOT * 8];   // packed h r-pairs [m][8]

// ---- packed f32x2 helpers (p2) ----
__device__ __forceinline__ ull pack2(float a, float b) {
    ull r; asm("mov.b64 %0, {%1, %2};" : "=l"(r) : "f"(a), "f"(b)); return r;
}
__device__ __forceinline__ void unpack2(ull v, float &a, float &b) {
    asm("mov.b64 {%0, %1}, %2;" : "=f"(a), "=f"(b) : "l"(v));
}
__device__ __forceinline__ ull fma2(ull a, ull b, ull c) {
    ull d; asm("fma.rn.f32x2 %0, %1, %2, %3;" : "=l"(d) : "l"(a), "l"(b), "l"(c)); return d;
}

// ---- async-copy helpers (sm_80 base ISA only) ----
__device__ __forceinline__ uint32_t smem_u32(const void* p) {
    uint32_t a;
    asm("{ .reg .u64 t; cvta.to.shared.u64 t, %1; cvt.u32.u64 %0, t; }"
        : "=r"(a) : "l"(p));
    return a;
}
__device__ __forceinline__ void cpa16(uint32_t dst, const void* src) {
    asm volatile("cp.async.cg.shared.global [%0], [%1], 16;"
                 :: "r"(dst), "l"(src) : "memory");
}
__device__ __forceinline__ void cpa_commit() {
    asm volatile("cp.async.commit_group;" ::: "memory");
}
__device__ __forceinline__ void cpa_wait1() {
    asm volatile("cp.async.wait_group 1;" ::: "memory");
}

// ---- tf32 mma helpers (base ISA, sm_80+) ----
__device__ __forceinline__ uint f2tf(float f) {   // round-to-nearest tf32
    uint r; asm("cvt.rna.tf32.f32 %0, %1;" : "=r"(r) : "f"(f)); return r;
}
__device__ __forceinline__ void mma8(float* d, uint a0, uint a1, uint a2, uint a3,
                                     uint b0, uint b1) {
    asm volatile(
        "mma.sync.aligned.m16n8k8.row.col.f32.tf32.tf32.f32 "
        "{%0,%1,%2,%3}, {%4,%5,%6,%7}, {%8,%9}, {%0,%1,%2,%3};"
        : "+f"(d[0]), "+f"(d[1]), "+f"(d[2]), "+f"(d[3])
        : "r"(a0), "r"(a1), "r"(a2), "r"(a3), "r"(b0), "r"(b1));
}

// ===================== kernel 1: h = SCALE * (x @ A^T), mma.sync tf32 =========
// 128 CTAs x 256 threads. Warp w: m16-tile (w&3), k-half (w>>2).
// smem (floats): xs[2][64][68] then raw A [2][16][68]. 43520 B static.
#define XSF(b)  ((b) * (64 * 68))
#define RAWF(b) (2 * 64 * 68 + (b) * (16 * 68))
#define SMEM_F  (2 * 64 * 68 + 2 * 16 * 68)    // 10880 floats

__device__ __forceinline__ void p1_stage(uint32_t sb, const float* x,
                                         const float* A, int m0, int c, int b,
                                         int tid) {
    #pragma unroll
    for (int t = 0; t < 4; ++t) {               // x: 64 rows x 16 units
        int u = tid + t * 256;
        int row = u >> 4, q = u & 15;
        cpa16(sb + (XSF(b) + row * 68) * 4 + q * 16,
              x + (size_t)(m0 + row) * D_IN + c * KC + q * 4);
    }
    {                                            // raw A: 16 rows x 16 units
        int row = tid >> 4, q = tid & 15;
        cpa16(sb + (RAWF(b) + row * 68) * 4 + q * 16,
              A + (size_t)row * D_IN + c * KC + q * 4);
    }
}

__global__ void __launch_bounds__(256, 2)
lora_mma1(const float* __restrict__ x, const float* __restrict__ A) {
    __shared__ __align__(16) float sm[SMEM_F];
    const uint32_t sb = smem_u32(sm);

    const int tid  = threadIdx.x;
    const int lane = tid & 31;
    const int warp = tid >> 5;
    const int wm   = warp & 3;       // m16 tile within 64-token CTA tile
    const int kh   = warp >> 2;      // k-half
    const int m0   = blockIdx.x * MT;
    const int r0   = lane >> 2;      // fragment row/col decomposition
    const int c0   = lane & 3;

    float d[4][4];                   // [ntile 0:hi0-7 1:hi8-15 2:lo0-7 3:lo8-15]
    #pragma unroll
    for (int nt = 0; nt < 4; ++nt)
        #pragma unroll
        for (int j = 0; j < 4; ++j) d[nt][j] = 0.0f;

    p1_stage(sb, x, A, m0, 0, 0, tid); cpa_commit();
    p1_stage(sb, x, A, m0, 1, 1, tid); cpa_commit();

    for (int i = 0; i < NITER; ++i) {
        const int b = i & 1;
        cpa_wait1();
        __syncthreads();

        const float* xw = sm + XSF(b) + (wm * 16) * 68;
        const float* rw = sm + RAWF(b);

        #pragma unroll
        for (int ks = 0; ks < 4; ++ks) {
            const int k0 = kh * 32 + ks * 8 + c0;
            // A-operand fragment: x rows (tf32-rounded, zero-mean rna)
            uint a0 = f2tf(xw[r0 * 68 + k0]);
            uint a1 = f2tf(xw[(r0 + 8) * 68 + k0]);
            uint a2 = f2tf(xw[r0 * 68 + k0 + 4]);
            uint a3 = f2tf(xw[(r0 + 8) * 68 + k0 + 4]);
            // B-operand: LoRA-A rows, hi/lo split in registers (hi exact tf32)
            float v00 = rw[r0 * 68 + k0];
            float v01 = rw[r0 * 68 + k0 + 4];
            float v10 = rw[(r0 + 8) * 68 + k0];
            float v11 = rw[(r0 + 8) * 68 + k0 + 4];
            uint h00 = __float_as_uint(v00) & 0xFFFFE000u;
            uint h01 = __float_as_uint(v01) & 0xFFFFE000u;
            uint h10 = __float_as_uint(v10) & 0xFFFFE000u;
            uint h11 = __float_as_uint(v11) & 0xFFFFE000u;
            float l00 = v00 - __uint_as_float(h00);
            float l01 = v01 - __uint_as_float(h01);
            float l10 = v10 - __uint_as_float(h10);
            float l11 = v11 - __uint_as_float(h11);
            mma8(d[0], a0, a1, a2, a3, h00, h01);
            mma8(d[1], a0, a1, a2, a3, h10, h11);
            mma8(d[2], a0, a1, a2, a3, __float_as_uint(l00), __float_as_uint(l01));
            mma8(d[3], a0, a1, a2, a3, __float_as_uint(l10), __float_as_uint(l11));
        }
        __syncthreads();

        if (i + 2 < NITER) p1_stage(sb, x, A, m0, i + 2, b, tid);
        cpa_commit();   // empty group near the end keeps wait_group counting
    }

    // k-half reduction via smem (xs region is free now)
    float* red = sm;
    if (kh == 1) {
        #pragma unroll
        for (int nt = 0; nt < 4; ++nt)
            #pragma unroll
            for (int j = 0; j < 4; ++j)
                red[wm * 512 + nt * 128 + j * 32 + lane] = d[nt][j];
    }
    __syncthreads();
    if (kh == 0) {
        #pragma unroll
        for (int nt = 0; nt < 4; ++nt)
            #pragma unroll
            for (int j = 0; j < 4; ++j)
                d[nt][j] += red[wm * 512 + nt * 128 + j * 32 + lane];

        // fold hi+lo, scale, pack, store.
        // D frag: reg0,1 -> row r0, cols 2c0,2c0+1 ; reg2,3 -> row r0+8.
        const int mlo = m0 + wm * 16 + r0;
        float e0 = (d[0][0] + d[2][0]) * SCALE, e1 = (d[0][1] + d[2][1]) * SCALE;
        float e2 = (d[0][2] + d[2][2]) * SCALE, e3 = (d[0][3] + d[2][3]) * SCALE;
        float f0 = (d[1][0] + d[3][0]) * SCALE, f1 = (d[1][1] + d[3][1]) * SCALE;
        float f2 = (d[1][2] + d[3][2]) * SCALE, f3 = (d[1][3] + d[3][3]) * SCALE;
        g_h[(size_t)mlo * 8 + c0]           = pack2(e0, e1);
        g_h[(size_t)mlo * 8 + 4 + c0]       = pack2(f0, f1);
        g_h[(size_t)(mlo + 8) * 8 + c0]     = pack2(e2, e3);
        g_h[(size_t)(mlo + 8) * 8 + 4 + c0] = pack2(f2, f3);
    }
}

// ===================== kernel 2: out = h @ B^T (R7-measured scalar) ==========
__global__ void __launch_bounds__(128, 5)
lora_p2(const float* __restrict__ B, float* __restrict__ out) {
    __shared__ __align__(16) ull sh[TOK2 * 8];   // 4 KB

    const int tid  = threadIdx.x;
    const int lane = tid & 31;
    const int warp = tid >> 5;
    const int o0   = blockIdx.y * 256 + warp * 64 + lane * 2;
    const int m0   = blockIdx.x * TOK2;

    ull b2[2][8];
    #pragma unroll
    for (int oo = 0; oo < 2; ++oo) {
        const ulonglong2* bp = (const ulonglong2*)(B + (size_t)(o0 + oo) * R_RANK);
        ulonglong2 q0 = bp[0], q1 = bp[1], q2 = bp[2], q3 = bp[3];
        b2[oo][0] = q0.x; b2[oo][1] = q0.y; b2[oo][2] = q1.x; b2[oo][3] = q1.y;
        b2[oo][4] = q2.x; b2[oo][5] = q2.y; b2[oo][6] = q3.x; b2[oo][7] = q3.y;
    }

    {
        const ulonglong2* src = (const ulonglong2*)(g_h + (size_t)m0 * 8);
        ulonglong2* dst = (ulonglong2*)sh;
        dst[tid]       = src[tid];
        dst[tid + 128] = src[tid + 128];
    }
    __syncthreads();

    #pragma unroll 4
    for (int t = 0; t < TOK2; t += 2) {
        const ulonglong2* hp0 = (const ulonglong2*)(sh + (t + 0) * 8);
        const ulonglong2* hp1 = (const ulonglong2*)(sh + (t + 1) * 8);
        ulonglong2 u0 = hp0[0], u1 = hp0[1], u2 = hp0[2], u3 = hp0[3];
        ulonglong2 w0 = hp1[0], w1 = hp1[1], w2 = hp1[2], w3 = hp1[3];
        ull ha[8] = {u0.x, u0.y, u1.x, u1.y, u2.x, u2.y, u3.x, u3.y};
        ull hb[8] = {w0.x, w0.y, w1.x, w1.y, w2.x, w2.y, w3.x, w3.y};

        ull s00 = 0ull, s01 = 0ull, s10 = 0ull, s11 = 0ull;
        #pragma unroll
        for (int p = 0; p < 8; ++p) {
            s00 = fma2(ha[p], b2[0][p], s00);
            s01 = fma2(ha[p], b2[1][p], s01);
            s10 = fma2(hb[p], b2[0][p], s10);
            s11 = fma2(hb[p], b2[1][p], s11);
        }
        float a, b, c, d;
        unpack2(s00, a, b); unpack2(s01, c, d);
        *(float2*)(out + (size_t)(m0 + t) * O_OUT + o0) = make_float2(a + b, c + d);
        unpack2(s10, a, b); unpack2(s11, c, d);
        *(float2*)(out + (size_t)(m0 + t + 1) * O_OUT + o0) = make_float2(a + b, c + d);
    }
}

extern "C" void kernel_launch(void* const* d_in, const int* in_sizes, int n_in,
                              void* d_out, int out_size) {
    const float* x = (const float*)d_in[0];
    const float* A = (const float*)d_in[1];   // [16, 4096]
    const float* B = (const float*)d_in[2];   // [4096, 16]
    float* out = (float*)d_out;

    lora_mma1<<<M_TOT / MT, 256>>>(x, A);     // 128 CTAs
    dim3 g2(M_TOT / TOK2, O_OUT / 256);       // (128, 16)
    lora_p2<<<g2, 128>>>(B, out);
}

// round 12
// speedup vs baseline: 1.0767x; 1.0767x over previous
#include <cuda_runtime.h>
#include <cstdint>

typedef unsigned long long ull;
typedef unsigned int uint;

#define D_IN   4096
#define R_RANK 16
#define O_OUT  4096
#define M_TOT  8192
#define SCALE  2.0f          // alpha/rank = 32/16
#define KC     64            // K floats per pipeline chunk
#define NITER  (D_IN / KC)   // 64
#define MT     32            // tokens per CTA (p1)
#define NSTG   4             // pipeline depth (p1)
#define TOK2   64            // tokens per CTA (p2)

// ---- device scratch ----
__device__ __align__(16) ull g_h[M_TOT * 8];   // packed h r-pairs [m][8]

// ---- packed f32x2 helpers (p2) ----
__device__ __forceinline__ ull pack2(float a, float b) {
    ull r; asm("mov.b64 %0, {%1, %2};" : "=l"(r) : "f"(a), "f"(b)); return r;
}
__device__ __forceinline__ void unpack2(ull v, float &a, float &b) {
    asm("mov.b64 {%0, %1}, %2;" : "=f"(a), "=f"(b) : "l"(v));
}
__device__ __forceinline__ ull fma2(ull a, ull b, ull c) {
    ull d; asm("fma.rn.f32x2 %0, %1, %2, %3;" : "=l"(d) : "l"(a), "l"(b), "l"(c)); return d;
}

// ---- async-copy helpers (sm_80 base ISA only) ----
__device__ __forceinline__ uint32_t smem_u32(const void* p) {
    uint32_t a;
    asm("{ .reg .u64 t; cvta.to.shared.u64 t, %1; cvt.u32.u64 %0, t; }"
        : "=r"(a) : "l"(p));
    return a;
}
__device__ __forceinline__ void cpa16(uint32_t dst, const void* src) {
    asm volatile("cp.async.cg.shared.global [%0], [%1], 16;"
                 :: "r"(dst), "l"(src) : "memory");
}
__device__ __forceinline__ void cpa_commit() {
    asm volatile("cp.async.commit_group;" ::: "memory");
}
__device__ __forceinline__ void cpa_wait2() {
    asm volatile("cp.async.wait_group 2;" ::: "memory");
}

// ---- tf32 mma helpers (base ISA, sm_80+) ----
__device__ __forceinline__ uint f2tf(float f) {   // round-to-nearest tf32
    uint r; asm("cvt.rna.tf32.f32 %0, %1;" : "=r"(r) : "f"(f)); return r;
}
__device__ __forceinline__ void mma8(float* d, uint a0, uint a1, uint a2, uint a3,
                                     uint b0, uint b1) {
    asm volatile(
        "mma.sync.aligned.m16n8k8.row.col.f32.tf32.tf32.f32 "
        "{%0,%1,%2,%3}, {%4,%5,%6,%7}, {%8,%9}, {%0,%1,%2,%3};"
        : "+f"(d[0]), "+f"(d[1]), "+f"(d[2]), "+f"(d[3])
        : "r"(a0), "r"(a1), "r"(a2), "r"(a3), "r"(b0), "r"(b1));
}

// ===================== kernel 1: h = SCALE * (x @ A^T), mma.sync tf32 =========
// 256 CTAs x 256 threads, MT=32 tokens/CTA, occ 2. Warp w: m16-tile (w&1),
// k-quarter (w>>1). 4-stage single-sync cp.async pipeline.
// Stage layout (floats): x[32][68] then raw A[16][68] -> 3264 floats/stage.
#define XS_F     (MT * 68)               // 2176
#define STAGE_F  (XS_F + 16 * 68)        // 3264 floats = 13056 B
#define SM1_B    (NSTG * STAGE_F * 4)    // 52224 B dynamic

__device__ __forceinline__ void p1_stage(uint32_t sb, const float* x,
                                         const float* A, int m0, int c, int b,
                                         int tid) {
    const uint32_t base = sb + b * (STAGE_F * 4);
    #pragma unroll
    for (int t = 0; t < 2; ++t) {               // x: 32 rows x 16 16B-units
        int u = tid + t * 256;
        int row = u >> 4, q = u & 15;
        cpa16(base + (row * 68) * 4 + q * 16,
              x + (size_t)(m0 + row) * D_IN + c * KC + q * 4);
    }
    {                                            // raw A: 16 rows x 16 units
        int row = tid >> 4, q = tid & 15;
        cpa16(base + (XS_F + row * 68) * 4 + q * 16,
              A + (size_t)row * D_IN + c * KC + q * 4);
    }
}

__global__ void __launch_bounds__(256, 2)
lora_mma1(const float* __restrict__ x, const float* __restrict__ A) {
    extern __shared__ __align__(16) float sm[];
    const uint32_t sb = smem_u32(sm);

    const int tid  = threadIdx.x;
    const int lane = tid & 31;
    const int warp = tid >> 5;
    const int wm   = warp & 1;       // m16 tile within 32-token CTA tile
    const int kh   = warp >> 1;      // k-quarter (0..3)
    const int m0   = blockIdx.x * MT;
    const int r0   = lane >> 2;
    const int c0   = lane & 3;

    float d[4][4];                   // [0:hi r0-7, 1:hi r8-15, 2:lo r0-7, 3:lo r8-15]
    #pragma unroll
    for (int nt = 0; nt < 4; ++nt)
        #pragma unroll
        for (int j = 0; j < 4; ++j) d[nt][j] = 0.0f;

    // prologue: stage chunks 0..2
    p1_stage(sb, x, A, m0, 0, 0, tid); cpa_commit();
    p1_stage(sb, x, A, m0, 1, 1, tid); cpa_commit();
    p1_stage(sb, x, A, m0, 2, 2, tid); cpa_commit();

    for (int i = 0; i < NITER; ++i) {
        const int b = i & 3;
        cpa_wait2();          // chunk i landed
        __syncthreads();      // visible to all; all warps past compute(i-1)

        // prefetch chunk i+3 into buffer (i+3)&3 == (i-1)&3 (freed by the sync)
        if (i + 3 < NITER) p1_stage(sb, x, A, m0, i + 3, (i + 3) & 3, tid);
        cpa_commit();

        const float* xw = sm + b * STAGE_F + (wm * 16) * 68;
        const float* rw = sm + b * STAGE_F + XS_F;

        #pragma unroll
        for (int ks = 0; ks < 2; ++ks) {
            const int k0 = kh * 16 + ks * 8 + c0;
            // A-operand fragment: x rows (tf32 rna, zero-mean)
            uint a0 = f2tf(xw[r0 * 68 + k0]);
            uint a1 = f2tf(xw[(r0 + 8) * 68 + k0]);
            uint a2 = f2tf(xw[r0 * 68 + k0 + 4]);
            uint a3 = f2tf(xw[(r0 + 8) * 68 + k0 + 4]);
            // B-operand: LoRA-A rows, hi/lo split (hi exact tf32)
            float v00 = rw[r0 * 68 + k0];
            float v01 = rw[r0 * 68 + k0 + 4];
            float v10 = rw[(r0 + 8) * 68 + k0];
            float v11 = rw[(r0 + 8) * 68 + k0 + 4];
            uint h00 = __float_as_uint(v00) & 0xFFFFE000u;
            uint h01 = __float_as_uint(v01) & 0xFFFFE000u;
            uint h10 = __float_as_uint(v10) & 0xFFFFE000u;
            uint h11 = __float_as_uint(v11) & 0xFFFFE000u;
            float l00 = v00 - __uint_as_float(h00);
            float l01 = v01 - __uint_as_float(h01);
            float l10 = v10 - __uint_as_float(h10);
            float l11 = v11 - __uint_as_float(h11);
            mma8(d[0], a0, a1, a2, a3, h00, h01);
            mma8(d[1], a0, a1, a2, a3, h10, h11);
            mma8(d[2], a0, a1, a2, a3, __float_as_uint(l00), __float_as_uint(l01));
            mma8(d[3], a0, a1, a2, a3, __float_as_uint(l10), __float_as_uint(l11));
        }
    }

    // k-quarter reduction via smem (buffers are dead now).
    // region: [(kh-1)*2 + wm][nt*128 + j*32 + lane], 3*2*512 floats.
    float* red = sm;
    if (kh != 0) {
        #pragma unroll
        for (int nt = 0; nt < 4; ++nt)
            #pragma unroll
            for (int j = 0; j < 4; ++j)
                red[((kh - 1) * 2 + wm) * 512 + nt * 128 + j * 32 + lane] = d[nt][j];
    }
    __syncthreads();
    if (kh == 0) {
        #pragma unroll
        for (int q = 0; q < 3; ++q)
            #pragma unroll
            for (int nt = 0; nt < 4; ++nt)
                #pragma unroll
                for (int j = 0; j < 4; ++j)
                    d[nt][j] += red[(q * 2 + wm) * 512 + nt * 128 + j * 32 + lane];

        // fold hi+lo, scale, pack, store (validated R11 mapping).
        const int mlo = m0 + wm * 16 + r0;
        float e0 = (d[0][0] + d[2][0]) * SCALE, e1 = (d[0][1] + d[2][1]) * SCALE;
        float e2 = (d[0][2] + d[2][2]) * SCALE, e3 = (d[0][3] + d[2][3]) * SCALE;
        float f0 = (d[1][0] + d[3][0]) * SCALE, f1 = (d[1][1] + d[3][1]) * SCALE;
        float f2 = (d[1][2] + d[3][2]) * SCALE, f3 = (d[1][3] + d[3][3]) * SCALE;
        g_h[(size_t)mlo * 8 + c0]           = pack2(e0, e1);
        g_h[(size_t)mlo * 8 + 4 + c0]       = pack2(f0, f1);
        g_h[(size_t)(mlo + 8) * 8 + c0]     = pack2(e2, e3);
        g_h[(size_t)(mlo + 8) * 8 + 4 + c0] = pack2(f2, f3);
    }
}

// ===================== kernel 2: out = h @ B^T (scalar FFMA2) ================
__global__ void __launch_bounds__(128, 6)
lora_p2(const float* __restrict__ B, float* __restrict__ out) {
    __shared__ __align__(16) ull sh[TOK2 * 8];   // 4 KB

    const int tid  = threadIdx.x;
    const int lane = tid & 31;
    const int warp = tid >> 5;
    const int o0   = blockIdx.y * 256 + warp * 64 + lane * 2;
    const int m0   = blockIdx.x * TOK2;

    ull b2[2][8];
    #pragma unroll
    for (int oo = 0; oo < 2; ++oo) {
        const ulonglong2* bp = (const ulonglong2*)(B + (size_t)(o0 + oo) * R_RANK);
        ulonglong2 q0 = bp[0], q1 = bp[1], q2 = bp[2], q3 = bp[3];
        b2[oo][0] = q0.x; b2[oo][1] = q0.y; b2[oo][2] = q1.x; b2[oo][3] = q1.y;
        b2[oo][4] = q2.x; b2[oo][5] = q2.y; b2[oo][6] = q3.x; b2[oo][7] = q3.y;
    }

    {
        const ulonglong2* src = (const ulonglong2*)(g_h + (size_t)m0 * 8);
        ulonglong2* dst = (ulonglong2*)sh;
        dst[tid]       = src[tid];
        dst[tid + 128] = src[tid + 128];
    }
    __syncthreads();

    #pragma unroll 2
    for (int t = 0; t < TOK2; t += 2) {
        const ulonglong2* hp0 = (const ulonglong2*)(sh + (t + 0) * 8);
        const ulonglong2* hp1 = (const ulonglong2*)(sh + (t + 1) * 8);
        ulonglong2 u0 = hp0[0], u1 = hp0[1], u2 = hp0[2], u3 = hp0[3];
        ulonglong2 w0 = hp1[0], w1 = hp1[1], w2 = hp1[2], w3 = hp1[3];
        ull ha[8] = {u0.x, u0.y, u1.x, u1.y, u2.x, u2.y, u3.x, u3.y};
        ull hb[8] = {w0.x, w0.y, w1.x, w1.y, w2.x, w2.y, w3.x, w3.y};

        ull s00 = 0ull, s01 = 0ull, s10 = 0ull, s11 = 0ull;
        #pragma unroll
        for (int p = 0; p < 8; ++p) {
            s00 = fma2(ha[p], b2[0][p], s00);
            s01 = fma2(ha[p], b2[1][p], s01);
            s10 = fma2(hb[p], b2[0][p], s10);
            s11 = fma2(hb[p], b2[1][p], s11);
        }
        float a, b, c, d;
        unpack2(s00, a, b); unpack2(s01, c, d);
        *(float2*)(out + (size_t)(m0 + t) * O_OUT + o0) = make_float2(a + b, c + d);
        unpack2(s10, a, b); unpack2(s11, c, d);
        *(float2*)(out + (size_t)(m0 + t + 1) * O_OUT + o0) = make_float2(a + b, c + d);
    }
}

extern "C" void kernel_launch(void* const* d_in, const int* in_sizes, int n_in,
                              void* d_out, int out_size) {
    const float* x = (const float*)d_in[0];
    const float* A = (const float*)d_in[1];   // [16, 4096]
    const float* B = (const float*)d_in[2];   // [4096, 16]
    float* out = (float*)d_out;

    cudaFuncSetAttribute(lora_mma1, cudaFuncAttributeMaxDynamicSharedMemorySize,
                         SM1_B);

    lora_mma1<<<M_TOT / MT, 256, SM1_B>>>(x, A);   // 256 CTAs
    dim3 g2(M_TOT / TOK2, O_OUT / 256);            // (128, 16)
    lora_p2<<<g2, 128>>>(B, out);
}